// round 3
// baseline (speedup 1.0000x reference)
#include <cuda_runtime.h>

// Problem constants (match setup_inputs exactly)
#define BATCH 64
#define IMG_H 1024
#define IMG_W 1024
#define NPTS  256
#define MAX_ITERS 20

// Scratch for converged end positions (device global: no allocations allowed)
__device__ int2 g_end[BATCH * NPTS];

// ---------------------------------------------------------------------------
// Kernel 1: fused smooth + gravity_move. One thread per point.
// Smoothed value s(y,x) = (1/9) * sum_{3x3} depth (zero pad). argmax over the
// 7x7 candidate window is scale-invariant, so we compare raw 3x3 sums.
// Fast path (point >=4 px from every border): separable 9-row streaming
// computation, 81 loads + ~280 FLOPs per iteration, fully in registers.
// Slow path (border): direct per-candidate evaluation with clamping +
// zero padding, duplicate clipped candidates resolved first-wins (matches
// jnp.argmax first-occurrence semantics).
// ---------------------------------------------------------------------------
__global__ __launch_bounds__(64)
void gravity_kernel(const float* __restrict__ depth,
                    const int*   __restrict__ points)
{
    int tid = blockIdx.x * blockDim.x + threadIdx.x;
    if (tid >= BATCH * NPTS) return;
    int b = tid >> 8;  // NPTS = 256

    const float* img = depth + (size_t)b * (IMG_H * IMG_W);

    int x = points[tid * 2 + 0];
    int y = points[tid * 2 + 1];

    for (int it = 0; it < MAX_ITERS; ++it) {
        int nx, ny;
        if (x >= 4 && x <= IMG_W - 5 && y >= 4 && y <= IMG_H - 5) {
            // ---- fast interior path: separable box sums ----
            const float* p = img + (size_t)(y - 4) * IMG_W + (x - 4);
            float C[3][7];            // rolling horizontal 3-sums for 3 rows
            float best = -__int_as_float(0x7f800000); // -inf
            int bk = 0;               // candidate index, row-major (dy,dx)
            #pragma unroll
            for (int r = 0; r < 9; ++r) {
                float v[9];
                #pragma unroll
                for (int c = 0; c < 9; ++c) v[c] = __ldg(p + r * IMG_W + c);
                #pragma unroll
                for (int c = 0; c < 7; ++c)
                    C[r % 3][c] = v[c] + v[c + 1] + v[c + 2];
                if (r >= 2) {
                    #pragma unroll
                    for (int c = 0; c < 7; ++c) {
                        float s = C[(r - 2) % 3][c] + C[(r - 1) % 3][c] + C[r % 3][c];
                        if (s > best) { best = s; bk = (r - 2) * 7 + c; }
                    }
                }
            }
            ny = y + bk / 7 - 3;
            nx = x + bk % 7 - 3;
        } else {
            // ---- border path: exact clamped/zero-padded evaluation ----
            float best = -__int_as_float(0x7f800000);
            int bx = x, by = y;
            for (int k = 0; k < 49; ++k) {
                int dy = k / 7 - 3;
                int dx = k % 7 - 3;
                int cy = min(max(y + dy, 0), IMG_H - 1);
                int cx = min(max(x + dx, 0), IMG_W - 1);
                float s = 0.0f;
                #pragma unroll
                for (int i = -1; i <= 1; ++i) {
                    #pragma unroll
                    for (int j = -1; j <= 1; ++j) {
                        int ry = cy + i, rx = cx + j;
                        if (ry >= 0 && ry < IMG_H && rx >= 0 && rx < IMG_W)
                            s += __ldg(img + (size_t)ry * IMG_W + rx);
                    }
                }
                if (s > best) { best = s; bx = cx; by = cy; }
            }
            nx = bx; ny = by;
        }
        if (nx == x && ny == y) break;   // per-point fixed point == global loop result
        x = nx; y = ny;
    }

    g_end[tid] = make_int2(x, y);
}

// ---------------------------------------------------------------------------
// Kernel 2: resolve_overlaps (exact integer arithmetic) + peak + output write.
// One block per batch, one thread per point.
//   ov[i][j]      = ||end_j - end_i||^2 < 4           (int, exact)
//   leader[i]     = first j with ov                   (argmax first-True)
//   winner[i]     = argmin_j over ov of ||start_j - end_i||^2 (first-min)
//   out[i]        = !has ? end_i : (i==winner[leader] ? end[leader] : start_i)
//   peak          = (1/9) * 3x3 raw sum at resolved position (zero pad)
// Output: f32 [end(B,N,2) | peak(B,N)] concatenated.
// ---------------------------------------------------------------------------
__global__ __launch_bounds__(NPTS)
void resolve_kernel(const float* __restrict__ depth,
                    const int*   __restrict__ points,
                    float*       __restrict__ out,
                    int out_size)
{
    __shared__ int ex[NPTS], ey[NPTS], sx[NPTS], sy[NPTS], win[NPTS];
    int b = blockIdx.x;
    int i = threadIdx.x;
    int gi = b * NPTS + i;

    int2 e = g_end[gi];
    ex[i] = e.x; ey[i] = e.y;
    sx[i] = points[gi * 2 + 0];
    sy[i] = points[gi * 2 + 1];
    __syncthreads();

    int eix = ex[i], eiy = ey[i];
    int cnt = 0, leader = -1, winner = 0;
    int bestd2 = 0x7fffffff;
    #pragma unroll 4
    for (int j = 0; j < NPTS; ++j) {
        int dxe = ex[j] - eix, dye = ey[j] - eiy;
        if (dxe * dxe + dye * dye < 4) {
            cnt++;
            if (leader < 0) leader = j;
            int dxs = sx[j] - eix, dys = sy[j] - eiy;
            int ds2 = dxs * dxs + dys * dys;
            if (ds2 < bestd2) { bestd2 = ds2; winner = j; }
        }
    }
    win[i] = winner;
    __syncthreads();

    int outx, outy;
    if (cnt > 1) {
        int wl = win[leader];
        if (i == wl) { outx = ex[leader]; outy = ey[leader]; }
        else         { outx = sx[i];      outy = sy[i]; }
    } else {
        outx = eix; outy = eiy;
    }

    // peak = smoothed depth at resolved position
    const float* img = depth + (size_t)b * (IMG_H * IMG_W);
    float s = 0.0f;
    #pragma unroll
    for (int di = -1; di <= 1; ++di) {
        #pragma unroll
        for (int dj = -1; dj <= 1; ++dj) {
            int ry = outy + di, rx = outx + dj;
            if (ry >= 0 && ry < IMG_H && rx >= 0 && rx < IMG_W)
                s += __ldg(img + (size_t)ry * IMG_W + rx);
        }
    }
    float peak = s * (1.0f / 9.0f);

    out[gi * 2 + 0] = (float)outx;
    out[gi * 2 + 1] = (float)outy;
    if (out_size >= BATCH * NPTS * 3)
        out[BATCH * NPTS * 2 + gi] = peak;
}

// ---------------------------------------------------------------------------
extern "C" void kernel_launch(void* const* d_in, const int* in_sizes, int n_in,
                              void* d_out, int out_size)
{
    // Disambiguate input order via element counts:
    // depth = 64*1*1024*1024 = 67108864 elems, points = 64*256*2 = 32768 elems
    const float* depth;
    const int*   points;
    if (in_sizes[0] > in_sizes[1]) {
        depth  = (const float*)d_in[0];
        points = (const int*)  d_in[1];
    } else {
        depth  = (const float*)d_in[1];
        points = (const int*)  d_in[0];
    }
    float* out = (float*)d_out;

    const int total = BATCH * NPTS;
    gravity_kernel<<<(total + 63) / 64, 64>>>(depth, points);
    resolve_kernel<<<BATCH, NPTS>>>(depth, points, out, out_size);
}

// round 4
// speedup vs baseline: 1.9388x; 1.9388x over previous
#include <cuda_runtime.h>

#define BATCH 64
#define IMG_H 1024
#define IMG_W 1024
#define NPTS  256
#define MAX_ITERS 20
#define TOTAL (BATCH * NPTS)

// Device scratch (no allocations allowed)
__device__ int2 g_end[TOTAL];
__device__ int  g_cnt[TOTAL];
__device__ int  g_leader[TOTAL];
__device__ int  g_winner[TOTAL];

// ---------------------------------------------------------------------------
// Kernel 1: fused smooth + gravity_move — ONE WARP PER POINT.
// The 7x7 candidate argmax over smoothed depth == argmax over raw 3x3 box
// sums (scale-invariant). The 9x9 zero-padded window centered at (y,x) covers
// every candidate's 3x3 stencil even under clamping (candidate coords lie in
// [y-3,y+3] clamped, stencil in [y-4,y+4]).
// Cooperative smem window load (<=3 coalesced loads/lane), 49 candidate sums
// spread over lanes, warp argmax with tie -> smallest candidate index
// (matches jnp.argmax first-occurrence; clamped duplicates are bitwise-equal
// so border cases are exact).
// Per-point fixed-point iteration (<=20) is equivalent to the reference's
// global while_loop: a stationary point stays stationary (validated R2).
// ---------------------------------------------------------------------------
__global__ __launch_bounds__(256)
void gravity_kernel(const float* __restrict__ depth,
                    const int*   __restrict__ points)
{
    __shared__ float swin[8][84];   // 9x9 window per warp (+pad)
    const int warp = threadIdx.x >> 5;
    const int lane = threadIdx.x & 31;
    const int p = (blockIdx.x << 3) + warp;   // grid = TOTAL/8 exactly
    const int b = p >> 8;
    const float* img = depth + (size_t)b * (IMG_H * IMG_W);
    float* w = swin[warp];

    int x = points[p * 2 + 0];
    int y = points[p * 2 + 1];

    // per-lane constants: window element coords + candidate offsets
    const int er0 = lane / 9,        ec0 = lane % 9;
    const int er1 = (lane + 32) / 9, ec1 = (lane + 32) % 9;
    const int er2 = (lane + 64) / 9, ec2 = (lane + 64) % 9;  // lanes < 17
    const int k1  = lane;      const int d1y = k1 / 7 - 3, d1x = k1 % 7 - 3;
    const int k2  = lane + 32; const int d2y = k2 / 7 - 3, d2x = k2 % 7 - 3;

    for (int it = 0; it < MAX_ITERS; ++it) {
        const int by0 = y - 4, bx0 = x - 4;

        // cooperative zero-padded window load
        {
            int ry = by0 + er0, rx = bx0 + ec0;
            w[lane] = (ry >= 0 && ry < IMG_H && rx >= 0 && rx < IMG_W)
                        ? __ldg(img + ry * IMG_W + rx) : 0.0f;
            ry = by0 + er1; rx = bx0 + ec1;
            w[lane + 32] = (ry >= 0 && ry < IMG_H && rx >= 0 && rx < IMG_W)
                        ? __ldg(img + ry * IMG_W + rx) : 0.0f;
            if (lane < 17) {
                ry = by0 + er2; rx = bx0 + ec2;
                w[lane + 64] = (ry >= 0 && ry < IMG_H && rx >= 0 && rx < IMG_W)
                        ? __ldg(img + ry * IMG_W + rx) : 0.0f;
            }
        }
        __syncwarp();

        // candidate sums (k1 for all lanes, k2 for lanes < 17)
        float bs; int bk;
        {
            int cy = min(max(y + d1y, 0), IMG_H - 1);
            int cx = min(max(x + d1x, 0), IMG_W - 1);
            int lr = cy - by0, lc = cx - bx0;   // in [1,7]
            float s = 0.0f;
            #pragma unroll
            for (int i = -1; i <= 1; ++i)
                #pragma unroll
                for (int j = -1; j <= 1; ++j)
                    s += w[(lr + i) * 9 + (lc + j)];
            bs = s; bk = k1;
        }
        if (lane < 17) {
            int cy = min(max(y + d2y, 0), IMG_H - 1);
            int cx = min(max(x + d2x, 0), IMG_W - 1);
            int lr = cy - by0, lc = cx - bx0;
            float s = 0.0f;
            #pragma unroll
            for (int i = -1; i <= 1; ++i)
                #pragma unroll
                for (int j = -1; j <= 1; ++j)
                    s += w[(lr + i) * 9 + (lc + j)];
            if (s > bs) { bs = s; bk = k2; }    // k2 > k1: tie keeps k1
        }
        // warp argmax: max value, tie -> smallest k
        #pragma unroll
        for (int off = 16; off; off >>= 1) {
            float os = __shfl_xor_sync(0xffffffffu, bs, off);
            int   ok = __shfl_xor_sync(0xffffffffu, bk, off);
            if (os > bs || (os == bs && ok < bk)) { bs = os; bk = ok; }
        }

        int ny = min(max(y + bk / 7 - 3, 0), IMG_H - 1);
        int nx = min(max(x + bk % 7 - 3, 0), IMG_W - 1);
        __syncwarp();                 // protect smem before next-iter writes
        if (nx == x && ny == y) break;  // warp-uniform
        x = nx; y = ny;
    }

    if (lane == 0) g_end[p] = make_int2(x, y);
}

// ---------------------------------------------------------------------------
// Kernel 2: pairwise overlap stats, exact integer arithmetic.
// grid = BATCH*8 blocks; block handles 32 points, 8 threads/point each
// scanning a 32-wide j-slice from smem. Partial (cnt, leader=min overlapping
// j, winner=lexmin (d2_start, j)) merged over the aligned 8-lane octet.
// dist < 2.0 on int coords  <=>  distSq < 4 (exact).
// ---------------------------------------------------------------------------
__global__ __launch_bounds__(256)
void pairs_kernel(const int* __restrict__ points)
{
    __shared__ int2 sE[NPTS], sS[NPTS];
    const int b = blockIdx.x >> 3;
    const int chunk = blockIdx.x & 7;
    const int t = threadIdx.x;
    {
        int gi = b * NPTS + t;
        sE[t] = g_end[gi];
        sS[t] = make_int2(points[gi * 2 + 0], points[gi * 2 + 1]);
    }
    __syncthreads();

    const int i   = chunk * 32 + (t >> 3);
    const int sub = t & 7;
    const int2 e = sE[i];

    int cnt = 0, leader = NPTS, winner = NPTS, bestd2 = 0x7fffffff;
    const int j0 = sub * 32;
    #pragma unroll 4
    for (int jj = 0; jj < 32; ++jj) {
        int j = j0 + jj;
        int2 ej = sE[j];
        int dx = ej.x - e.x, dy = ej.y - e.y;
        if (dx * dx + dy * dy < 4) {
            cnt++;
            leader = min(leader, j);
            int2 sj = sS[j];
            int ax = sj.x - e.x, ay = sj.y - e.y;
            int d2 = ax * ax + ay * ay;
            if (d2 < bestd2 || (d2 == bestd2 && j < winner)) { bestd2 = d2; winner = j; }
        }
    }
    // merge across the aligned 8-lane octet
    #pragma unroll
    for (int off = 4; off; off >>= 1) {
        int oc = __shfl_down_sync(0xffffffffu, cnt,    off);
        int ol = __shfl_down_sync(0xffffffffu, leader, off);
        int od = __shfl_down_sync(0xffffffffu, bestd2, off);
        int ow = __shfl_down_sync(0xffffffffu, winner, off);
        cnt += oc;
        leader = min(leader, ol);
        if (od < bestd2 || (od == bestd2 && ow < winner)) { bestd2 = od; winner = ow; }
    }
    if (sub == 0) {
        int gi = b * NPTS + i;
        g_cnt[gi] = cnt; g_leader[gi] = leader; g_winner[gi] = winner;
    }
}

// ---------------------------------------------------------------------------
// Kernel 3: finalize — resolve via win[leader], compute peak, write output.
// Output layout (f32): [end(B,N,2) | peak(B,N)].
// ---------------------------------------------------------------------------
__global__ __launch_bounds__(256)
void finalize_kernel(const float* __restrict__ depth,
                     const int*   __restrict__ points,
                     float*       __restrict__ out,
                     int out_size)
{
    const int gi = blockIdx.x * 256 + threadIdx.x;
    const int b  = gi >> 8;
    const int i  = gi & 255;

    int outx, outy;
    int2 e = g_end[gi];
    if (g_cnt[gi] > 1) {
        int leader = g_leader[gi];
        int wl = g_winner[b * NPTS + leader];
        if (i == wl) {
            int2 el = g_end[b * NPTS + leader];
            outx = el.x; outy = el.y;
        } else {
            outx = points[gi * 2 + 0];
            outy = points[gi * 2 + 1];
        }
    } else {
        outx = e.x; outy = e.y;
    }

    const float* img = depth + (size_t)b * (IMG_H * IMG_W);
    float s = 0.0f;
    #pragma unroll
    for (int di = -1; di <= 1; ++di)
        #pragma unroll
        for (int dj = -1; dj <= 1; ++dj) {
            int ry = outy + di, rx = outx + dj;
            if (ry >= 0 && ry < IMG_H && rx >= 0 && rx < IMG_W)
                s += __ldg(img + ry * IMG_W + rx);
        }

    out[gi * 2 + 0] = (float)outx;
    out[gi * 2 + 1] = (float)outy;
    if (out_size >= TOTAL * 3)
        out[TOTAL * 2 + gi] = s * (1.0f / 9.0f);
}

// ---------------------------------------------------------------------------
extern "C" void kernel_launch(void* const* d_in, const int* in_sizes, int n_in,
                              void* d_out, int out_size)
{
    const float* depth;
    const int*   points;
    if (in_sizes[0] > in_sizes[1]) {
        depth  = (const float*)d_in[0];
        points = (const int*)  d_in[1];
    } else {
        depth  = (const float*)d_in[1];
        points = (const int*)  d_in[0];
    }
    float* out = (float*)d_out;

    gravity_kernel <<<TOTAL / 8, 256>>>(depth, points);
    pairs_kernel   <<<BATCH * 8, 256>>>(points);
    finalize_kernel<<<BATCH,     256>>>(depth, points, out, out_size);
}

// round 5
// speedup vs baseline: 2.5220x; 1.3008x over previous
#include <cuda_runtime.h>

#define BATCH 64
#define IMG_H 1024
#define IMG_W 1024
#define NPTS  256
#define MAX_ITERS 20
#define TOTAL (BATCH * NPTS)

// Device scratch (no allocations allowed)
__device__ int2 g_end[TOTAL];

// Order-preserving float->uint map (total order, matches float > on non-NaN)
__device__ __forceinline__ unsigned ordkey(float f) {
    unsigned u = __float_as_uint(f);
    return (u & 0x80000000u) ? ~u : (u | 0x80000000u);
}

// ---------------------------------------------------------------------------
// Kernel 1: fused smooth + gravity_move — one warp per point.
// argmax over 7x7 candidates of smoothed depth == argmax of raw 3x3 box sums.
// 9x9 zero-padded window in per-warp smem; 49 candidate sums over 32 lanes;
// warp argmax via REDUX (max key, then min candidate index among maxima =
// jnp.argmax first-occurrence; clamped duplicate candidates are bitwise-equal
// so min-index wins exactly as in the reference).
// Per-point fixed-point iteration == reference's global while_loop (validated).
// ---------------------------------------------------------------------------
__global__ __launch_bounds__(256)
void gravity_kernel(const float* __restrict__ depth,
                    const int*   __restrict__ points)
{
    __shared__ float swin[8][84];   // 81 + pad
    const int warp = threadIdx.x >> 5;
    const int lane = threadIdx.x & 31;
    const int p = (blockIdx.x << 3) + warp;       // grid = TOTAL/8 exactly
    const int b = p >> 8;
    const float* img = depth + (size_t)b * (IMG_H * IMG_W);
    float* w = swin[warp];

    int x = points[p * 2 + 0];
    int y = points[p * 2 + 1];

    // per-lane constants
    const int er0 = lane / 9,        ec0 = lane % 9;
    const int er1 = (lane + 32) / 9, ec1 = (lane + 32) % 9;
    const int er2 = (lane + 64) / 9, ec2 = (lane + 64) % 9;   // lanes < 17
    const int k1  = lane;      const int d1y = k1 / 7 - 3, d1x = k1 % 7 - 3;
    const int k2  = lane + 32; const int d2y = k2 / 7 - 3, d2x = k2 % 7 - 3;

    for (int it = 0; it < MAX_ITERS; ++it) {
        const int by0 = y - 4, bx0 = x - 4;
        const float* base = img + (size_t)by0 * IMG_W + bx0;
        // warp-uniform branch: unpredicated loads for interior (common case)
        if (x >= 4 && x <= IMG_W - 5 && y >= 4 && y <= IMG_H - 5) {
            w[lane]      = __ldg(base + er0 * IMG_W + ec0);
            w[lane + 32] = __ldg(base + er1 * IMG_W + ec1);
            if (lane < 17)
                w[lane + 64] = __ldg(base + er2 * IMG_W + ec2);
        } else {
            int ry = by0 + er0, rx = bx0 + ec0;
            w[lane] = (ry >= 0 && ry < IMG_H && rx >= 0 && rx < IMG_W)
                        ? __ldg(img + ry * IMG_W + rx) : 0.0f;
            ry = by0 + er1; rx = bx0 + ec1;
            w[lane + 32] = (ry >= 0 && ry < IMG_H && rx >= 0 && rx < IMG_W)
                        ? __ldg(img + ry * IMG_W + rx) : 0.0f;
            if (lane < 17) {
                ry = by0 + er2; rx = bx0 + ec2;
                w[lane + 64] = (ry >= 0 && ry < IMG_H && rx >= 0 && rx < IMG_W)
                        ? __ldg(img + ry * IMG_W + rx) : 0.0f;
            }
        }
        __syncwarp();

        // candidate 1 (all lanes)
        unsigned ub; int bk;
        {
            int cy = min(max(y + d1y, 0), IMG_H - 1);
            int cx = min(max(x + d1x, 0), IMG_W - 1);
            const float* q = w + (cy - by0) * 9 + (cx - bx0);
            float s = q[-10] + q[-9] + q[-8]
                    + q[-1]  + q[0]  + q[1]
                    + q[8]   + q[9]  + q[10];
            ub = ordkey(s); bk = k1;
        }
        // candidate 2 (lanes < 17)
        if (lane < 17) {
            int cy = min(max(y + d2y, 0), IMG_H - 1);
            int cx = min(max(x + d2x, 0), IMG_W - 1);
            const float* q = w + (cy - by0) * 9 + (cx - bx0);
            float s = q[-10] + q[-9] + q[-8]
                    + q[-1]  + q[0]  + q[1]
                    + q[8]   + q[9]  + q[10];
            unsigned u2 = ordkey(s);
            if (u2 > ub) { ub = u2; bk = k2; }   // tie keeps k1 (smaller)
        }

        // warp argmax: max key, then min index among maxima
        unsigned umax = __reduce_max_sync(0xffffffffu, ub);
        int bkg = (int)__reduce_min_sync(0xffffffffu,
                        (ub == umax) ? (unsigned)bk : 64u);

        int ny = min(max(y + bkg / 7 - 3, 0), IMG_H - 1);
        int nx = min(max(x + bkg % 7 - 3, 0), IMG_W - 1);
        __syncwarp();                  // protect smem before next-iter writes
        if (nx == x && ny == y) break; // warp-uniform (bkg uniform)
        x = nx; y = ny;
    }

    if (lane == 0) g_end[p] = make_int2(x, y);
}

// ---------------------------------------------------------------------------
// Kernel 2: fused resolve_overlaps + peak + output. One block per batch.
// Phase A: 2 threads per point, each scans a 128-wide j-slice in smem,
//   exact int arithmetic (dist<2.0 <=> distSq<4). Merge via shfl_xor(1).
// Phase B: threads 0..255 resolve win[leader] dependence, compute peak
//   (zero-padded 3x3/9), write f32 output [end(B,N,2) | peak(B,N)].
// ---------------------------------------------------------------------------
__global__ __launch_bounds__(512)
void resolve_kernel(const float* __restrict__ depth,
                    const int*   __restrict__ points,
                    float*       __restrict__ out,
                    int out_size)
{
    __shared__ int2 sE[NPTS], sS[NPTS];
    __shared__ int  sCnt[NPTS], sLead[NPTS], sWin[NPTS];
    const int b = blockIdx.x;
    const int t = threadIdx.x;

    if (t < NPTS) {
        int gi = b * NPTS + t;
        sE[t] = g_end[gi];
        sS[t] = make_int2(points[gi * 2 + 0], points[gi * 2 + 1]);
    }
    __syncthreads();

    // ---- Phase A: pairwise stats ----
    {
        const int i   = t >> 1;
        const int sub = t & 1;
        const int2 e = sE[i];
        int cnt = 0, leader = NPTS, winner = NPTS, bestd2 = 0x7fffffff;
        const int j0 = sub * 128;
        #pragma unroll 4
        for (int jj = 0; jj < 128; ++jj) {
            int j = j0 + jj;
            int2 ej = sE[j];
            int dx = ej.x - e.x, dy = ej.y - e.y;
            if (dx * dx + dy * dy < 4) {
                cnt++;
                leader = min(leader, j);
                int2 sj = sS[j];
                int ax = sj.x - e.x, ay = sj.y - e.y;
                int d2 = ax * ax + ay * ay;
                if (d2 < bestd2 || (d2 == bestd2 && j < winner)) {
                    bestd2 = d2; winner = j;
                }
            }
        }
        // merge the two slices (t and t^1 are in the same warp)
        int oc = __shfl_xor_sync(0xffffffffu, cnt,    1);
        int ol = __shfl_xor_sync(0xffffffffu, leader, 1);
        int od = __shfl_xor_sync(0xffffffffu, bestd2, 1);
        int ow = __shfl_xor_sync(0xffffffffu, winner, 1);
        cnt += oc;
        leader = min(leader, ol);
        if (od < bestd2 || (od == bestd2 && ow < winner)) {
            bestd2 = od; winner = ow;
        }
        if (sub == 0) { sCnt[i] = cnt; sLead[i] = leader; sWin[i] = winner; }
    }
    __syncthreads();

    // ---- Phase B: finalize + peak + write ----
    if (t < NPTS) {
        const int i  = t;
        const int gi = b * NPTS + i;
        int outx, outy;
        if (sCnt[i] > 1) {
            int leader = sLead[i];
            if (i == sWin[leader]) {
                outx = sE[leader].x; outy = sE[leader].y;
            } else {
                outx = sS[i].x; outy = sS[i].y;
            }
        } else {
            outx = sE[i].x; outy = sE[i].y;
        }

        const float* img = depth + (size_t)b * (IMG_H * IMG_W);
        float s = 0.0f;
        #pragma unroll
        for (int di = -1; di <= 1; ++di)
            #pragma unroll
            for (int dj = -1; dj <= 1; ++dj) {
                int ry = outy + di, rx = outx + dj;
                if (ry >= 0 && ry < IMG_H && rx >= 0 && rx < IMG_W)
                    s += __ldg(img + ry * IMG_W + rx);
            }

        out[gi * 2 + 0] = (float)outx;
        out[gi * 2 + 1] = (float)outy;
        if (out_size >= TOTAL * 3)
            out[TOTAL * 2 + gi] = s * (1.0f / 9.0f);
    }
}

// ---------------------------------------------------------------------------
extern "C" void kernel_launch(void* const* d_in, const int* in_sizes, int n_in,
                              void* d_out, int out_size)
{
    const float* depth;
    const int*   points;
    if (in_sizes[0] > in_sizes[1]) {
        depth  = (const float*)d_in[0];
        points = (const int*)  d_in[1];
    } else {
        depth  = (const float*)d_in[1];
        points = (const int*)  d_in[0];
    }
    float* out = (float*)d_out;

    gravity_kernel<<<TOTAL / 8, 256>>>(depth, points);
    resolve_kernel<<<BATCH, 512>>>(depth, points, out, out_size);
}

// round 6
// speedup vs baseline: 2.5254x; 1.0014x over previous
#include <cuda_runtime.h>

#define BATCH 64
#define IMG_H 1024
#define IMG_W 1024
#define NPTS  256
#define MAX_ITERS 20
#define TOTAL (BATCH * NPTS)

// Device scratch (no allocations allowed)
__device__ int2 g_end[TOTAL];
__device__ int  g_cnt[TOTAL];
__device__ int  g_leader[TOTAL];
__device__ int  g_winner[TOTAL];

// Order-preserving float->uint map (total order, matches float > on non-NaN)
__device__ __forceinline__ unsigned ordkey(float f) {
    unsigned u = __float_as_uint(f);
    return (u & 0x80000000u) ? ~u : (u | 0x80000000u);
}

// ---------------------------------------------------------------------------
// Kernel 1: fused smooth + gravity_move — one warp per point.
// argmax over 7x7 candidates of smoothed depth == argmax of raw 3x3 box sums.
// 9x9 zero-padded window in per-warp smem. Interior fast path: ALL addressing
// (window-load offsets and candidate smem offsets) is loop-invariant per lane
// and hoisted out of the iteration loop. Warp argmax via REDUX: max ordkey,
// then min candidate index among maxima == jnp.argmax first-occurrence
// (clamped duplicate candidates are bitwise-equal, so min-index is exact).
// Per-point fixed-point iteration == reference global while_loop (validated).
// ---------------------------------------------------------------------------
__global__ __launch_bounds__(256)
void gravity_kernel(const float* __restrict__ depth,
                    const int*   __restrict__ points)
{
    __shared__ float swin[8][84];   // 81 + pad
    const int warp = threadIdx.x >> 5;
    const int lane = threadIdx.x & 31;
    const int p = (blockIdx.x << 3) + warp;       // grid = TOTAL/8 exactly
    const int b = p >> 8;
    const float* img = depth + (size_t)b * (IMG_H * IMG_W);
    float* w = swin[warp];

    int x = points[p * 2 + 0];
    int y = points[p * 2 + 1];

    // ---- loop-invariant per-lane constants ----
    const int er0 = lane / 9,        ec0 = lane % 9;
    const int er1 = (lane + 32) / 9, ec1 = (lane + 32) % 9;
    const int er2 = (lane + 64) / 9, ec2 = (lane + 64) % 9;   // lanes < 17
    const int off0 = er0 * IMG_W + ec0;          // global window-load offsets
    const int off1 = er1 * IMG_W + ec1;
    const int off2 = er2 * IMG_W + ec2;
    const int k1  = lane;      const int d1y = k1 / 7 - 3, d1x = k1 % 7 - 3;
    const int k2  = lane + 32; const int d2y = k2 / 7 - 3, d2x = k2 % 7 - 3;
    const int qoff1 = (d1y + 4) * 9 + (d1x + 4); // interior candidate offsets
    const int qoff2 = (d2y + 4) * 9 + (d2x + 4);

    for (int it = 0; it < MAX_ITERS; ++it) {
        const int by0 = y - 4, bx0 = x - 4;
        const bool interior = (x >= 4) & (x <= IMG_W - 5) &
                              (y >= 4) & (y <= IMG_H - 5); // warp-uniform
        unsigned ub; int bk;

        if (interior) {
            const float* base = img + by0 * IMG_W + bx0;
            w[lane]      = __ldg(base + off0);
            w[lane + 32] = __ldg(base + off1);
            if (lane < 17)
                w[lane + 64] = __ldg(base + off2);
            __syncwarp();

            {
                const float* q = w + qoff1;   // fixed per-lane address
                float s = q[-10] + q[-9] + q[-8]
                        + q[-1]  + q[0]  + q[1]
                        + q[8]   + q[9]  + q[10];
                ub = ordkey(s); bk = k1;
            }
            if (lane < 17) {
                const float* q = w + qoff2;
                float s = q[-10] + q[-9] + q[-8]
                        + q[-1]  + q[0]  + q[1]
                        + q[8]   + q[9]  + q[10];
                unsigned u2 = ordkey(s);
                if (u2 > ub) { ub = u2; bk = k2; }   // tie keeps smaller k1
            }
        } else {
            // ---- border path: zero-padded load + clamped candidates ----
            int ry = by0 + er0, rx = bx0 + ec0;
            w[lane] = (ry >= 0 && ry < IMG_H && rx >= 0 && rx < IMG_W)
                        ? __ldg(img + ry * IMG_W + rx) : 0.0f;
            ry = by0 + er1; rx = bx0 + ec1;
            w[lane + 32] = (ry >= 0 && ry < IMG_H && rx >= 0 && rx < IMG_W)
                        ? __ldg(img + ry * IMG_W + rx) : 0.0f;
            if (lane < 17) {
                ry = by0 + er2; rx = bx0 + ec2;
                w[lane + 64] = (ry >= 0 && ry < IMG_H && rx >= 0 && rx < IMG_W)
                        ? __ldg(img + ry * IMG_W + rx) : 0.0f;
            }
            __syncwarp();

            {
                int cy = min(max(y + d1y, 0), IMG_H - 1);
                int cx = min(max(x + d1x, 0), IMG_W - 1);
                const float* q = w + (cy - by0) * 9 + (cx - bx0);
                float s = q[-10] + q[-9] + q[-8]
                        + q[-1]  + q[0]  + q[1]
                        + q[8]   + q[9]  + q[10];
                ub = ordkey(s); bk = k1;
            }
            if (lane < 17) {
                int cy = min(max(y + d2y, 0), IMG_H - 1);
                int cx = min(max(x + d2x, 0), IMG_W - 1);
                const float* q = w + (cy - by0) * 9 + (cx - bx0);
                float s = q[-10] + q[-9] + q[-8]
                        + q[-1]  + q[0]  + q[1]
                        + q[8]   + q[9]  + q[10];
                unsigned u2 = ordkey(s);
                if (u2 > ub) { ub = u2; bk = k2; }
            }
        }

        // warp argmax: max key, then min index among maxima
        unsigned umax = __reduce_max_sync(0xffffffffu, ub);
        int bkg = (int)__reduce_min_sync(0xffffffffu,
                        (ub == umax) ? (unsigned)bk : 64u);

        int ny = min(max(y + bkg / 7 - 3, 0), IMG_H - 1);
        int nx = min(max(x + bkg % 7 - 3, 0), IMG_W - 1);
        __syncwarp();                  // protect smem before next-iter writes
        if (nx == x && ny == y) break; // warp-uniform
        x = nx; y = ny;
    }

    if (lane == 0) g_end[p] = make_int2(x, y);
}

// ---------------------------------------------------------------------------
// Kernel 2: pairwise overlap stats — full-chip spread + SIMD halfword math.
// grid = BATCH*4 blocks (256), block = 512 threads: 64 points/block,
// 8 threads/point each scanning 32 j's from smem.
// Coords packed (y<<16)|x. On int coords, distSq<4 <=> Chebyshev<=1, tested
// with one __vabsdiffu2 + mask. Partial (cnt, min leader j, lexmin
// (startD2, j) winner) merged over the aligned 8-lane octet — all exact int.
// ---------------------------------------------------------------------------
__global__ __launch_bounds__(512)
void pairs_kernel(const int* __restrict__ points)
{
    __shared__ int sE[NPTS], sS[NPTS];
    const int b = blockIdx.x >> 2;
    const int chunk = blockIdx.x & 3;
    const int t = threadIdx.x;
    if (t < NPTS) {
        int gi = b * NPTS + t;
        int2 e = g_end[gi];
        sE[t] = e.x | (e.y << 16);
        sS[t] = points[gi * 2 + 0] | (points[gi * 2 + 1] << 16);
    }
    __syncthreads();

    const int i   = chunk * 64 + (t >> 3);
    const int sub = t & 7;
    const int ei = sE[i];
    const int ex = ei & 0xFFFF, ey = ei >> 16;

    int cnt = 0, leader = NPTS, winner = NPTS, bestd2 = 0x7fffffff;
    const int j0 = sub * 32;
    #pragma unroll 8
    for (int jj = 0; jj < 32; ++jj) {
        int j = j0 + jj;
        unsigned d = __vabsdiffu2((unsigned)ei, (unsigned)sE[j]);
        if ((d & 0xFFFEFFFEu) == 0u) {        // both |dx|,|dy| <= 1
            cnt++;
            leader = min(leader, j);
            int sj = sS[j];
            int ax = (sj & 0xFFFF) - ex, ay = (sj >> 16) - ey;
            int d2 = ax * ax + ay * ay;
            if (d2 < bestd2 || (d2 == bestd2 && j < winner)) {
                bestd2 = d2; winner = j;
            }
        }
    }
    // merge across aligned 8-lane octet
    #pragma unroll
    for (int off = 4; off; off >>= 1) {
        int oc = __shfl_down_sync(0xffffffffu, cnt,    off);
        int ol = __shfl_down_sync(0xffffffffu, leader, off);
        int od = __shfl_down_sync(0xffffffffu, bestd2, off);
        int ow = __shfl_down_sync(0xffffffffu, winner, off);
        cnt += oc;
        leader = min(leader, ol);
        if (od < bestd2 || (od == bestd2 && ow < winner)) {
            bestd2 = od; winner = ow;
        }
    }
    if (sub == 0) {
        int gi = b * NPTS + i;
        g_cnt[gi] = cnt; g_leader[gi] = leader; g_winner[gi] = winner;
    }
}

// ---------------------------------------------------------------------------
// Kernel 3: finalize — win[leader] resolution, peak, output write.
// Output layout (f32): [end(B,N,2) | peak(B,N)].
// ---------------------------------------------------------------------------
__global__ __launch_bounds__(128)
void finalize_kernel(const float* __restrict__ depth,
                     const int*   __restrict__ points,
                     float*       __restrict__ out,
                     int out_size)
{
    const int gi = blockIdx.x * 128 + threadIdx.x;
    const int b  = gi >> 8;
    const int i  = gi & 255;

    int outx, outy;
    int2 e = g_end[gi];
    if (g_cnt[gi] > 1) {
        int leader = g_leader[gi];
        if (i == g_winner[b * NPTS + leader]) {
            int2 el = g_end[b * NPTS + leader];
            outx = el.x; outy = el.y;
        } else {
            outx = points[gi * 2 + 0];
            outy = points[gi * 2 + 1];
        }
    } else {
        outx = e.x; outy = e.y;
    }

    const float* img = depth + (size_t)b * (IMG_H * IMG_W);
    float s = 0.0f;
    #pragma unroll
    for (int di = -1; di <= 1; ++di)
        #pragma unroll
        for (int dj = -1; dj <= 1; ++dj) {
            int ry = outy + di, rx = outx + dj;
            if (ry >= 0 && ry < IMG_H && rx >= 0 && rx < IMG_W)
                s += __ldg(img + ry * IMG_W + rx);
        }

    out[gi * 2 + 0] = (float)outx;
    out[gi * 2 + 1] = (float)outy;
    if (out_size >= TOTAL * 3)
        out[TOTAL * 2 + gi] = s * (1.0f / 9.0f);
}

// ---------------------------------------------------------------------------
extern "C" void kernel_launch(void* const* d_in, const int* in_sizes, int n_in,
                              void* d_out, int out_size)
{
    const float* depth;
    const int*   points;
    if (in_sizes[0] > in_sizes[1]) {
        depth  = (const float*)d_in[0];
        points = (const int*)  d_in[1];
    } else {
        depth  = (const float*)d_in[1];
        points = (const int*)  d_in[0];
    }
    float* out = (float*)d_out;

    gravity_kernel <<<TOTAL / 8, 256>>>(depth, points);
    pairs_kernel   <<<BATCH * 4, 512>>>(points);
    finalize_kernel<<<TOTAL / 128, 128>>>(depth, points, out, out_size);
}